// round 4
// baseline (speedup 1.0000x reference)
#include <cuda_runtime.h>

// LCC over [B=2,1,192,192,192] fp32, fully fused z-sweep.
// Round-4: single barrier per plane (merged stepP/box2 smem phases),
// full-iteration load prefetch distance, float2 + packed f32x2 math.

namespace {
constexpr int NV   = 192;
constexpr int NV2  = NV * NV;
constexpr long long NV3 = (long long)NV * NV2;
constexpr int BYT  = 8;
constexpr int RY   = 2;
constexpr int COVY = BYT * RY;      // 16 covered rows
constexpr int TOUTX = 48;           // outputs/block in x (lanes cover 64)
constexpr int TOUTY = COVY - 4;     // 12
constexpr int ZCHUNKS = 8;
constexpr int ZC   = NV / ZCHUNKS;  // 24 (divisible by 3)
constexpr float EPSV  = 1e-5f;
constexpr float INV27 = 1.0f / 27.0f;
constexpr unsigned FULL = 0xffffffffu;
}

__device__ __forceinline__ float2 a2(float2 a, float2 b) {
    float2 r;
    asm("{.reg .b64 ra,rb,rc;\n\t"
        "mov.b64 ra,{%2,%3};\n\t"
        "mov.b64 rb,{%4,%5};\n\t"
        "add.rn.f32x2 rc,ra,rb;\n\t"
        "mov.b64 {%0,%1},rc;}\n\t"
        : "=f"(r.x), "=f"(r.y)
        : "f"(a.x), "f"(a.y), "f"(b.x), "f"(b.y));
    return r;
}
__device__ __forceinline__ float2 m2(float2 a, float2 b) {
    float2 r;
    asm("{.reg .b64 ra,rb,rc;\n\t"
        "mov.b64 ra,{%2,%3};\n\t"
        "mov.b64 rb,{%4,%5};\n\t"
        "mul.rn.f32x2 rc,ra,rb;\n\t"
        "mov.b64 {%0,%1},rc;}\n\t"
        : "=f"(r.x), "=f"(r.y)
        : "f"(a.x), "f"(a.y), "f"(b.x), "f"(b.y));
    return r;
}
__device__ __forceinline__ float2 f2ma(float2 a, float2 b, float2 c) {
    float2 r;
    asm("{.reg .b64 ra,rb,rc,rd;\n\t"
        "mov.b64 ra,{%2,%3};\n\t"
        "mov.b64 rb,{%4,%5};\n\t"
        "mov.b64 rc,{%6,%7};\n\t"
        "fma.rn.f32x2 rd,ra,rb,rc;\n\t"
        "mov.b64 {%0,%1},rd;}\n\t"
        : "=f"(r.x), "=f"(r.y)
        : "f"(a.x), "f"(a.y), "f"(b.x), "f"(b.y), "f"(c.x), "f"(c.y));
    return r;
}

__global__ void zero_out_kernel(float* out, int n) {
    int i = blockIdx.x * blockDim.x + threadIdx.x;
    if (i < n) out[i] = 0.0f;
}

__global__ __launch_bounds__(256, 3)
void lcc_kernel(const float* __restrict__ gF,
                const float* __restrict__ gM,
                float* __restrict__ out)
{
    __shared__ float2 sA [2][COVY][33];
    __shared__ float2 sB [2][COVY][33];
    __shared__ float2 sQ0[2][COVY][33];
    __shared__ float2 sQ1[2][COVY][33];
    __shared__ float2 sQ2[2][COVY][33];
    __shared__ float  wsum[BYT];

    const int tx  = threadIdx.x;
    const int ty  = threadIdx.y;
    const int yl0 = ty * RY;
    const int b   = blockIdx.z / ZCHUNKS;
    const int Z0  = (blockIdx.z % ZCHUNKS) * ZC;

    const int x_nom0 = (int)blockIdx.x * TOUTX - 2 + 2 * tx;   // even
    const int xbase  = min(max(x_nom0, 0), NV - 2);
    const bool fixlo  = (x_nom0 < 0);
    const bool fixhi  = (x_nom0 > NV - 2);
    const bool fixXlo = (x_nom0 == 0);
    const bool fixXhi = (x_nom0 + 1 == NV - 1);

    const int y_nom0 = (int)blockIdx.y * TOUTY - 2 + yl0;
    const bool fixYup = (y_nom0 == 0);
    const bool fixYdn = (y_nom0 + 1 == NV - 1);

    int yoff[RY];
#pragma unroll
    for (int i = 0; i < RY; i++)
        yoff[i] = min(max(y_nom0 + i, 0), NV - 1) * NV;

    const float* F = gF + (long long)b * NV3;
    const float* M = gM + (long long)b * NV3;

    float2 rF[3][RY], rM[3][RY];               // raw plane ring
    float2 pA[3][RY], pB[3][RY], pC[3][RY];    // P plane ring (FM, FF, MM)
    float2 acc = make_float2(0.f, 0.f);
    int sp = 0;

    const float2 NEGI = make_float2(-INV27, -INV27);
    const float2 EPS2 = make_float2(EPSV, EPSV);

    const bool okl = (tx >= 1 && tx <= 24);
    float mrow[RY];
#pragma unroll
    for (int i = 0; i < RY; i++) {
        int yloc = yl0 + i;
        mrow[i] = (okl && yloc >= 2 && yloc < 2 + TOUTY) ? 1.0f : 0.0f;
    }

    auto loadp = [&](int z, float2 (&oF)[RY], float2 (&oM)[RY]) {
        z = min(max(z, 0), NV - 1);
        const float* fp = F + z * NV2;
        const float* mp = M + z * NV2;
#pragma unroll
        for (int i = 0; i < RY; i++) {
            float2 vF = __ldg(reinterpret_cast<const float2*>(fp + yoff[i] + xbase));
            float2 vM = __ldg(reinterpret_cast<const float2*>(mp + yoff[i] + xbase));
            oF[i].x = fixhi ? vF.y : vF.x;  oF[i].y = fixlo ? vF.x : vF.y;
            oM[i].x = fixhi ? vM.y : vM.x;  oM[i].y = fixlo ? vM.x : vM.y;
        }
    };

    const int rup = yl0 ? yl0 - 1 : 0;
    const int rdn = (yl0 + RY < COVY) ? yl0 + RY : COVY - 1;

    // Prologue P-step: P for plane in slot ic (ip,ic,in_ = j-1,j,j+1) -> slot qw.
    auto stepP_pro = [&](int ip, int ic, int in_, int qw) {
        float2 zf[RY], zm[RY];
#pragma unroll
        for (int i = 0; i < RY; i++) {
            zf[i] = a2(a2(rF[ip][i], rF[ic][i]), rF[in_][i]);
            zm[i] = a2(a2(rM[ip][i], rM[ic][i]), rM[in_][i]);
            sA[sp][yl0 + i][tx] = zf[i];
            sB[sp][yl0 + i][tx] = zm[i];
        }
        __syncthreads();
        float2 upF = sA[sp][rup][tx], dnF = sA[sp][rdn][tx];
        float2 upM = sB[sp][rup][tx], dnM = sB[sp][rdn][tx];
        float2 yf[RY], ym[RY];
        yf[0] = a2(a2(upF, zf[0]), zf[1]);  yf[1] = a2(a2(zf[0], zf[1]), dnF);
        ym[0] = a2(a2(upM, zm[0]), zm[1]);  ym[1] = a2(a2(zm[0], zm[1]), dnM);
#pragma unroll
        for (int i = 0; i < RY; i++) {
            float lF = __shfl_up_sync(FULL, yf[i].y, 1);
            float rG = __shfl_down_sync(FULL, yf[i].x, 1);
            float pF = yf[i].x + yf[i].y;
            float2 sF = make_float2(lF + pF, pF + rG);
            float lM = __shfl_up_sync(FULL, ym[i].y, 1);
            float rH = __shfl_down_sync(FULL, ym[i].x, 1);
            float pM = ym[i].x + ym[i].y;
            float2 sM = make_float2(lM + pM, pM + rH);
            float2 dF = f2ma(sF, NEGI, rF[ic][i]);
            float2 dM = f2ma(sM, NEGI, rM[ic][i]);
            pA[qw][i] = m2(dF, dM);
            pB[qw][i] = m2(dF, dF);
            pC[qw][i] = m2(dM, dM);
        }
        sp ^= 1;
    };

    // ---- Prologue: raw slots end as (0:Z0+1, 1:Z0+2, 2:Z0+3); P slots P(Z0-1..Z0+1) ----
    if (Z0 == 0) {
        loadp(0, rF[2], rM[2]);
        loadp(1, rF[0], rM[0]);
        stepP_pro(2, 2, 0, 1);   // P(0): z-sum = 2*F(0)+F(1) (replicate)
#pragma unroll
        for (int i = 0; i < RY; i++) {  // P(-1) := P(0)
            pA[0][i] = pA[1][i]; pB[0][i] = pB[1][i]; pC[0][i] = pC[1][i];
        }
        loadp(2, rF[1], rM[1]);
        stepP_pro(2, 0, 1, 2);   // P(1)
        loadp(3, rF[2], rM[2]);
    } else {
        loadp(Z0 - 2, rF[0], rM[0]);
        loadp(Z0 - 1, rF[1], rM[1]);
        loadp(Z0,     rF[2], rM[2]);
        stepP_pro(0, 1, 2, 0);   // P(Z0-1)
        loadp(Z0 + 1, rF[0], rM[0]);
        stepP_pro(1, 2, 0, 1);   // P(Z0)
        loadp(Z0 + 2, rF[1], rM[1]);
        stepP_pro(2, 0, 1, 2);   // P(Z0+1)
        loadp(Z0 + 3, rF[2], rM[2]);
    }

    const int zlast = Z0 + ZC - 1;

    // ---- Main body: one __syncthreads per plane ----
    // entry: raw r[s0]=j+1, r[s1]=j+2, r[s2]=j+3; P p[s0]=P(j-1), p[s1]=P(j), p[s2]=P(j+1)
    auto body = [&](int j, int s0, int s1, int s2) {
        float2 zf[RY], zm[RY];
#pragma unroll
        for (int i = 0; i < RY; i++) {
            zf[i] = a2(a2(rF[s0][i], rF[s1][i]), rF[s2][i]);   // plane j+2 z-sums
            zm[i] = a2(a2(rM[s0][i], rM[s1][i]), rM[s2][i]);
        }
        loadp(j + 4, rF[s0], rM[s0]);   // prefetch (consumed next iteration)
#pragma unroll
        for (int i = 0; i < RY; i++) {
            float2 zA = a2(a2(pA[s0][i], pA[s1][i]), pA[s2][i]);
            float2 zB = a2(a2(pB[s0][i], pB[s1][i]), pB[s2][i]);
            float2 zD = a2(a2(pC[s0][i], pC[s1][i]), pC[s2][i]);
            sQ0[sp][yl0 + i][tx] = zA;
            sQ1[sp][yl0 + i][tx] = zB;
            sQ2[sp][yl0 + i][tx] = zD;
            sA[sp][yl0 + i][tx]  = zf[i];
            sB[sp][yl0 + i][tx]  = zm[i];
        }
        __syncthreads();

        // ---- box2 tail: score output plane j ----
        {
            float2 uA = sQ0[sp][rup][tx], oA0 = sQ0[sp][yl0][tx],
                   oA1 = sQ0[sp][yl0 + 1][tx], dA = sQ0[sp][rdn][tx];
            float2 uB = sQ1[sp][rup][tx], oB0 = sQ1[sp][yl0][tx],
                   oB1 = sQ1[sp][yl0 + 1][tx], dB = sQ1[sp][rdn][tx];
            float2 uD = sQ2[sp][rup][tx], oD0 = sQ2[sp][yl0][tx],
                   oD1 = sQ2[sp][yl0 + 1][tx], dD = sQ2[sp][rdn][tx];
            uA = fixYup ? oA0 : uA;  dA = fixYdn ? oA1 : dA;
            uB = fixYup ? oB0 : uB;  dB = fixYdn ? oB1 : dB;
            uD = fixYup ? oD0 : uD;  dD = fixYdn ? oD1 : dD;
            float2 ybA[RY], ybB[RY], ybD[RY];
            ybA[0] = a2(a2(uA, oA0), oA1);  ybA[1] = a2(a2(oA0, oA1), dA);
            ybB[0] = a2(a2(uB, oB0), oB1);  ybB[1] = a2(a2(oB0, oB1), dB);
            ybD[0] = a2(a2(uD, oD0), oD1);  ybD[1] = a2(a2(oD0, oD1), dD);
#pragma unroll
            for (int i = 0; i < RY; i++) {
                float lA = __shfl_up_sync(FULL, ybA[i].y, 1);
                float rA = __shfl_down_sync(FULL, ybA[i].x, 1);
                float pA_ = ybA[i].x + ybA[i].y;
                float2 crA = make_float2((fixXlo ? ybA[i].x : lA) + pA_,
                                         pA_ + (fixXhi ? ybA[i].y : rA));
                float lB = __shfl_up_sync(FULL, ybB[i].y, 1);
                float rB = __shfl_down_sync(FULL, ybB[i].x, 1);
                float pB_ = ybB[i].x + ybB[i].y;
                float2 crB = make_float2((fixXlo ? ybB[i].x : lB) + pB_,
                                         pB_ + (fixXhi ? ybB[i].y : rB));
                float lD = __shfl_up_sync(FULL, ybD[i].y, 1);
                float rD = __shfl_down_sync(FULL, ybD[i].x, 1);
                float pD_ = ybD[i].x + ybD[i].y;
                float2 crD = make_float2((fixXlo ? ybD[i].x : lD) + pD_,
                                         pD_ + (fixXhi ? ybD[i].y : rD));
                float2 num = m2(crA, crA);
                float2 den = f2ma(crB, crD, EPS2);
                float2 zv  = make_float2(__fdividef(num.x, den.x),
                                         __fdividef(num.y, den.y));
                acc = f2ma(zv, make_float2(mrow[i], mrow[i]), acc);
            }
        }

        // ---- stepP tail: P(j+2) -> slot s0 ----
        if (j < zlast) {
            if (j + 2 < NV) {
                float2 upF = sA[sp][rup][tx], dnF = sA[sp][rdn][tx];
                float2 upM = sB[sp][rup][tx], dnM = sB[sp][rdn][tx];
                float2 yf[RY], ym[RY];
                yf[0] = a2(a2(upF, zf[0]), zf[1]);  yf[1] = a2(a2(zf[0], zf[1]), dnF);
                ym[0] = a2(a2(upM, zm[0]), zm[1]);  ym[1] = a2(a2(zm[0], zm[1]), dnM);
#pragma unroll
                for (int i = 0; i < RY; i++) {
                    float lF = __shfl_up_sync(FULL, yf[i].y, 1);
                    float rG = __shfl_down_sync(FULL, yf[i].x, 1);
                    float pF = yf[i].x + yf[i].y;
                    float2 sF = make_float2(lF + pF, pF + rG);
                    float lM = __shfl_up_sync(FULL, ym[i].y, 1);
                    float rH = __shfl_down_sync(FULL, ym[i].x, 1);
                    float pM = ym[i].x + ym[i].y;
                    float2 sM = make_float2(lM + pM, pM + rH);
                    float2 dF = f2ma(sF, NEGI, rF[s1][i]);
                    float2 dM = f2ma(sM, NEGI, rM[s1][i]);
                    pA[s0][i] = m2(dF, dM);
                    pB[s0][i] = m2(dF, dF);
                    pC[s0][i] = m2(dM, dM);
                }
            } else {
#pragma unroll
                for (int i = 0; i < RY; i++) {   // P(j+2) := P(NV-1)
                    pA[s0][i] = pA[s2][i];
                    pB[s0][i] = pB[s2][i];
                    pC[s0][i] = pC[s2][i];
                }
            }
        }
        sp ^= 1;
    };

    for (int kb = 0; kb < ZC; kb += 3) {
        body(Z0 + kb,     0, 1, 2);
        body(Z0 + kb + 1, 1, 2, 0);
        body(Z0 + kb + 2, 2, 0, 1);
    }

    // ---- Reduction ----
    float t = acc.x + acc.y;
#pragma unroll
    for (int o = 16; o > 0; o >>= 1)
        t += __shfl_xor_sync(FULL, t, o);
    if (tx == 0) wsum[ty] = t;
    __syncthreads();
    if (tx == 0 && ty == 0) {
        float s = 0.0f;
#pragma unroll
        for (int i = 0; i < BYT; i++) s += wsum[i];
        atomicAdd(&out[b], s * (-1.0f / (float)NV3));
    }
}

extern "C" void kernel_launch(void* const* d_in, const int* in_sizes, int n_in,
                              void* d_out, int out_size) {
    const float* F = (const float*)d_in[0];
    const float* M = (const float*)d_in[1];
    float* out = (float*)d_out;

    const int B = (int)(in_sizes[0] / (long long)NV3);

    zero_out_kernel<<<1, 32>>>(out, out_size);

    dim3 block(32, BYT, 1);
    dim3 grid(NV / TOUTX, NV / TOUTY, B * ZCHUNKS);
    lcc_kernel<<<grid, block>>>(F, M, out);
}

// round 5
// speedup vs baseline: 1.4475x; 1.4475x over previous
#include <cuda_runtime.h>

// LCC over [B=2,1,192,192,192] fp32, fully fused z-sweep.
// Round-5: round-3 two-phase ordering + streaming P-state (S,L instead of a
// 3-slot P ring, -12 regs), single-buffered smem, launch_bounds(256,4)
// -> 4 CTAs/SM.

namespace {
constexpr int NV   = 192;
constexpr int NV2  = NV * NV;
constexpr long long NV3 = (long long)NV * NV2;
constexpr int BYT  = 8;
constexpr int RY   = 2;
constexpr int COVY = BYT * RY;      // 16 covered rows
constexpr int TOUTX = 48;           // outputs/block in x (lanes cover 64)
constexpr int TOUTY = COVY - 4;     // 12
constexpr int ZCHUNKS = 8;
constexpr int ZC   = NV / ZCHUNKS;  // 24 (divisible by 3)
constexpr float EPSV  = 1e-5f;
constexpr float INV27 = 1.0f / 27.0f;
constexpr unsigned FULL = 0xffffffffu;
}

__device__ __forceinline__ float2 a2(float2 a, float2 b) {
    float2 r;
    asm("{.reg .b64 ra,rb,rc;\n\t"
        "mov.b64 ra,{%2,%3};\n\t"
        "mov.b64 rb,{%4,%5};\n\t"
        "add.rn.f32x2 rc,ra,rb;\n\t"
        "mov.b64 {%0,%1},rc;}\n\t"
        : "=f"(r.x), "=f"(r.y)
        : "f"(a.x), "f"(a.y), "f"(b.x), "f"(b.y));
    return r;
}
__device__ __forceinline__ float2 m2(float2 a, float2 b) {
    float2 r;
    asm("{.reg .b64 ra,rb,rc;\n\t"
        "mov.b64 ra,{%2,%3};\n\t"
        "mov.b64 rb,{%4,%5};\n\t"
        "mul.rn.f32x2 rc,ra,rb;\n\t"
        "mov.b64 {%0,%1},rc;}\n\t"
        : "=f"(r.x), "=f"(r.y)
        : "f"(a.x), "f"(a.y), "f"(b.x), "f"(b.y));
    return r;
}
__device__ __forceinline__ float2 f2ma(float2 a, float2 b, float2 c) {
    float2 r;
    asm("{.reg .b64 ra,rb,rc,rd;\n\t"
        "mov.b64 ra,{%2,%3};\n\t"
        "mov.b64 rb,{%4,%5};\n\t"
        "mov.b64 rc,{%6,%7};\n\t"
        "fma.rn.f32x2 rd,ra,rb,rc;\n\t"
        "mov.b64 {%0,%1},rd;}\n\t"
        : "=f"(r.x), "=f"(r.y)
        : "f"(a.x), "f"(a.y), "f"(b.x), "f"(b.y), "f"(c.x), "f"(c.y));
    return r;
}

__global__ void zero_out_kernel(float* out, int n) {
    int i = blockIdx.x * blockDim.x + threadIdx.x;
    if (i < n) out[i] = 0.0f;
}

__global__ __launch_bounds__(256, 4)
void lcc_kernel(const float* __restrict__ gF,
                const float* __restrict__ gM,
                float* __restrict__ out)
{
    __shared__ float2 sA [COVY][33];
    __shared__ float2 sB [COVY][33];
    __shared__ float2 sQ0[COVY][33];
    __shared__ float2 sQ1[COVY][33];
    __shared__ float2 sQ2[COVY][33];
    __shared__ float  wsum[BYT];

    const int tx  = threadIdx.x;
    const int ty  = threadIdx.y;
    const int yl0 = ty * RY;
    const int b   = blockIdx.z / ZCHUNKS;
    const int Z0  = (blockIdx.z % ZCHUNKS) * ZC;

    const int x_nom0 = (int)blockIdx.x * TOUTX - 2 + 2 * tx;   // even
    const int xbase  = min(max(x_nom0, 0), NV - 2);
    const bool fixlo  = (x_nom0 < 0);
    const bool fixhi  = (x_nom0 > NV - 2);
    const bool fixXlo = (x_nom0 == 0);
    const bool fixXhi = (x_nom0 + 1 == NV - 1);

    const int y_nom0 = (int)blockIdx.y * TOUTY - 2 + yl0;
    const bool fixYup = (y_nom0 == 0);
    const bool fixYdn = (y_nom0 + 1 == NV - 1);

    int yoff[RY];
#pragma unroll
    for (int i = 0; i < RY; i++)
        yoff[i] = min(max(y_nom0 + i, 0), NV - 1) * NV + xbase;

    const float* F = gF + (long long)b * NV3;
    const float* M = gM + (long long)b * NV3;

    float2 rF[3][RY], rM[3][RY];                  // raw plane ring
    float2 sFM[RY], sFF[RY], sMM[RY];             // S = P(j-1)+P(j)
    float2 lFM[RY], lFF[RY], lMM[RY];             // L = P(j)
    float2 nFM[RY], nFF[RY], nMM[RY];             // Pn = P(j+1)
    float2 acc = make_float2(0.f, 0.f);

    const float2 NEGI = make_float2(-INV27, -INV27);
    const float2 EPS2 = make_float2(EPSV, EPSV);

    const bool okl = (tx >= 1 && tx <= 24);
    float mrow[RY];
#pragma unroll
    for (int i = 0; i < RY; i++) {
        int yloc = yl0 + i;
        mrow[i] = (okl && yloc >= 2 && yloc < 2 + TOUTY) ? 1.0f : 0.0f;
    }

    auto loadp = [&](int z, int s) {
        z = min(z, NV - 1);
        const float* fp = F + z * NV2;
        const float* mp = M + z * NV2;
#pragma unroll
        for (int i = 0; i < RY; i++) {
            float2 vF = __ldg(reinterpret_cast<const float2*>(fp + yoff[i]));
            float2 vM = __ldg(reinterpret_cast<const float2*>(mp + yoff[i]));
            rF[s][i].x = fixhi ? vF.y : vF.x;  rF[s][i].y = fixlo ? vF.x : vF.y;
            rM[s][i].x = fixhi ? vM.y : vM.x;  rM[s][i].y = fixlo ? vM.x : vM.y;
        }
    };

    const int rup = yl0 ? yl0 - 1 : 0;
    const int rdn = (yl0 + RY < COVY) ? yl0 + RY : COVY - 1;

    // Pn = P(plane in slot i1); ring (i0,i1,i2) holds planes c-1,c,c+1.
    // Issues prefetch of plane `loadz` into slot `ls` (never i1) between the
    // smem stores and the barrier.
    auto makeP = [&](int i0, int i1, int i2, int loadz, int ls, bool tailbar) {
        float2 zf[RY], zm[RY];
#pragma unroll
        for (int i = 0; i < RY; i++) {
            zf[i] = a2(a2(rF[i0][i], rF[i1][i]), rF[i2][i]);
            zm[i] = a2(a2(rM[i0][i], rM[i1][i]), rM[i2][i]);
            sA[yl0 + i][tx] = zf[i];
            sB[yl0 + i][tx] = zm[i];
        }
        loadp(loadz, ls);
        __syncthreads();
        float2 upF = sA[rup][tx], dnF = sA[rdn][tx];
        float2 upM = sB[rup][tx], dnM = sB[rdn][tx];
        float2 yf[RY], ym[RY];
        yf[0] = a2(a2(upF, zf[0]), zf[1]);  yf[1] = a2(a2(zf[0], zf[1]), dnF);
        ym[0] = a2(a2(upM, zm[0]), zm[1]);  ym[1] = a2(a2(zm[0], zm[1]), dnM);
#pragma unroll
        for (int i = 0; i < RY; i++) {
            float lF = __shfl_up_sync(FULL, yf[i].y, 1);
            float rG = __shfl_down_sync(FULL, yf[i].x, 1);
            float pF = yf[i].x + yf[i].y;
            float2 sF = make_float2(lF + pF, pF + rG);
            float lM = __shfl_up_sync(FULL, ym[i].y, 1);
            float rH = __shfl_down_sync(FULL, ym[i].x, 1);
            float pM = ym[i].x + ym[i].y;
            float2 sM = make_float2(lM + pM, pM + rH);
            float2 dF = f2ma(sF, NEGI, rF[i1][i]);
            float2 dM = f2ma(sM, NEGI, rM[i1][i]);
            nFM[i] = m2(dF, dM);
            nFF[i] = m2(dF, dF);
            nMM[i] = m2(dM, dM);
        }
        if (tailbar) __syncthreads();
    };

    // ---- Prologue: S=P(Z0-1)+P(Z0), L=P(Z0); ring ends (r2=Z0, r0=Z0+1, r1=Z0+2) ----
    if (Z0 == 0) {
        loadp(0, 2);
        loadp(1, 0);
        makeP(2, 2, 0, 2, 1, true);    // P(0): zsum=2*r(0)+r(1), center r(0)
#pragma unroll
        for (int i = 0; i < RY; i++) {
            lFM[i] = nFM[i]; lFF[i] = nFF[i]; lMM[i] = nMM[i];
            sFM[i] = a2(nFM[i], nFM[i]);   // P(-1)=P(0)
            sFF[i] = a2(nFF[i], nFF[i]);
            sMM[i] = a2(nMM[i], nMM[i]);
        }
    } else {
        loadp(Z0 - 2, 0);
        loadp(Z0 - 1, 1);
        loadp(Z0,     2);
        makeP(0, 1, 2, Z0 + 1, 0, true);   // P(Z0-1)
#pragma unroll
        for (int i = 0; i < RY; i++) { sFM[i] = nFM[i]; sFF[i] = nFF[i]; sMM[i] = nMM[i]; }
        makeP(1, 2, 0, Z0 + 2, 1, true);   // P(Z0)
#pragma unroll
        for (int i = 0; i < RY; i++) {
            lFM[i] = nFM[i]; lFF[i] = nFF[i]; lMM[i] = nMM[i];
            sFM[i] = a2(sFM[i], nFM[i]);
            sFF[i] = a2(sFF[i], nFF[i]);
            sMM[i] = a2(sMM[i], nMM[i]);
        }
    }

    // ---- Main body: entry ring (s0,s1,s2) = planes (j, j+1, j+2) ----
    auto body = [&](int j, int s0, int s1, int s2) {
        if (j + 1 < NV) {
            makeP(s0, s1, s2, j + 3, s0, false);   // Pn = P(j+1), prefetch j+3
        } else {
            __syncthreads();                        // keep smem phase discipline
#pragma unroll
            for (int i = 0; i < RY; i++) {          // P(NV) := P(NV-1)
                nFM[i] = lFM[i]; nFF[i] = lFF[i]; nMM[i] = lMM[i];
            }
        }

        float2 zA[RY], zB[RY], zD[RY];
#pragma unroll
        for (int i = 0; i < RY; i++) {
            zA[i] = a2(sFM[i], nFM[i]);
            zB[i] = a2(sFF[i], nFF[i]);
            zD[i] = a2(sMM[i], nMM[i]);
            sQ0[yl0 + i][tx] = zA[i];
            sQ1[yl0 + i][tx] = zB[i];
            sQ2[yl0 + i][tx] = zD[i];
        }
        // streaming state update (kills Pn early)
#pragma unroll
        for (int i = 0; i < RY; i++) {
            sFM[i] = a2(lFM[i], nFM[i]);  lFM[i] = nFM[i];
            sFF[i] = a2(lFF[i], nFF[i]);  lFF[i] = nFF[i];
            sMM[i] = a2(lMM[i], nMM[i]);  lMM[i] = nMM[i];
        }
        __syncthreads();

        float2 uA = sQ0[rup][tx], dA = sQ0[rdn][tx];
        float2 uB = sQ1[rup][tx], dB = sQ1[rdn][tx];
        float2 uD = sQ2[rup][tx], dD = sQ2[rdn][tx];
        uA = fixYup ? zA[0] : uA;  dA = fixYdn ? zA[1] : dA;
        uB = fixYup ? zB[0] : uB;  dB = fixYdn ? zB[1] : dB;
        uD = fixYup ? zD[0] : uD;  dD = fixYdn ? zD[1] : dD;
        float2 ybA[RY], ybB[RY], ybD[RY];
        ybA[0] = a2(a2(uA, zA[0]), zA[1]);  ybA[1] = a2(a2(zA[0], zA[1]), dA);
        ybB[0] = a2(a2(uB, zB[0]), zB[1]);  ybB[1] = a2(a2(zB[0], zB[1]), dB);
        ybD[0] = a2(a2(uD, zD[0]), zD[1]);  ybD[1] = a2(a2(zD[0], zD[1]), dD);
#pragma unroll
        for (int i = 0; i < RY; i++) {
            float lA = __shfl_up_sync(FULL, ybA[i].y, 1);
            float rA = __shfl_down_sync(FULL, ybA[i].x, 1);
            float pA_ = ybA[i].x + ybA[i].y;
            float2 crA = make_float2((fixXlo ? ybA[i].x : lA) + pA_,
                                     pA_ + (fixXhi ? ybA[i].y : rA));
            float lB = __shfl_up_sync(FULL, ybB[i].y, 1);
            float rB = __shfl_down_sync(FULL, ybB[i].x, 1);
            float pB_ = ybB[i].x + ybB[i].y;
            float2 crB = make_float2((fixXlo ? ybB[i].x : lB) + pB_,
                                     pB_ + (fixXhi ? ybB[i].y : rB));
            float lD = __shfl_up_sync(FULL, ybD[i].y, 1);
            float rD = __shfl_down_sync(FULL, ybD[i].x, 1);
            float pD_ = ybD[i].x + ybD[i].y;
            float2 crD = make_float2((fixXlo ? ybD[i].x : lD) + pD_,
                                     pD_ + (fixXhi ? ybD[i].y : rD));
            float2 num = m2(crA, crA);
            float2 den = f2ma(crB, crD, EPS2);
            float2 zv  = make_float2(__fdividef(num.x, den.x),
                                     __fdividef(num.y, den.y));
            acc = f2ma(zv, make_float2(mrow[i], mrow[i]), acc);
        }
    };

    for (int kb = 0; kb < ZC; kb += 3) {
        body(Z0 + kb,     2, 0, 1);
        body(Z0 + kb + 1, 0, 1, 2);
        body(Z0 + kb + 2, 1, 2, 0);
    }

    // ---- Reduction ----
    float t = acc.x + acc.y;
#pragma unroll
    for (int o = 16; o > 0; o >>= 1)
        t += __shfl_xor_sync(FULL, t, o);
    if (tx == 0) wsum[ty] = t;
    __syncthreads();
    if (tx == 0 && ty == 0) {
        float s = 0.0f;
#pragma unroll
        for (int i = 0; i < BYT; i++) s += wsum[i];
        atomicAdd(&out[b], s * (-1.0f / (float)NV3));
    }
}

extern "C" void kernel_launch(void* const* d_in, const int* in_sizes, int n_in,
                              void* d_out, int out_size) {
    const float* F = (const float*)d_in[0];
    const float* M = (const float*)d_in[1];
    float* out = (float*)d_out;

    const int B = (int)(in_sizes[0] / (long long)NV3);

    zero_out_kernel<<<1, 32>>>(out, out_size);

    dim3 block(32, BYT, 1);
    dim3 grid(NV / TOUTX, NV / TOUTY, B * ZCHUNKS);
    lcc_kernel<<<grid, block>>>(F, M, out);
}

// round 6
// speedup vs baseline: 1.5655x; 1.0816x over previous
#include <cuda_runtime.h>

// LCC over [B=2,1,192,192,192] fp32, fully fused z-sweep.
// Round-6: RY=1, 512-thread blocks (32x16), ring-P round-3 structure.
// Natural regs ~55-60 -> 2 CTAs/SM (32 warps, 50% occ) with no spills.

namespace {
constexpr int NV   = 192;
constexpr int NV2  = NV * NV;
constexpr long long NV3 = (long long)NV * NV2;
constexpr int BYT  = 16;            // warps per block (each owns 1 row)
constexpr int COVY = 16;            // covered rows
constexpr int TOUTX = 48;           // outputs/block in x (lanes cover 64)
constexpr int TOUTY = 12;           // outputs/block in y
constexpr int ZCHUNKS = 8;
constexpr int ZC   = NV / ZCHUNKS;  // 24 (divisible by 3)
constexpr float EPSV  = 1e-5f;
constexpr float INV27 = 1.0f / 27.0f;
constexpr unsigned FULL = 0xffffffffu;
}

__device__ __forceinline__ float2 a2(float2 a, float2 b) {
    float2 r;
    asm("{.reg .b64 ra,rb,rc;\n\t"
        "mov.b64 ra,{%2,%3};\n\t"
        "mov.b64 rb,{%4,%5};\n\t"
        "add.rn.f32x2 rc,ra,rb;\n\t"
        "mov.b64 {%0,%1},rc;}\n\t"
        : "=f"(r.x), "=f"(r.y)
        : "f"(a.x), "f"(a.y), "f"(b.x), "f"(b.y));
    return r;
}
__device__ __forceinline__ float2 m2(float2 a, float2 b) {
    float2 r;
    asm("{.reg .b64 ra,rb,rc;\n\t"
        "mov.b64 ra,{%2,%3};\n\t"
        "mov.b64 rb,{%4,%5};\n\t"
        "mul.rn.f32x2 rc,ra,rb;\n\t"
        "mov.b64 {%0,%1},rc;}\n\t"
        : "=f"(r.x), "=f"(r.y)
        : "f"(a.x), "f"(a.y), "f"(b.x), "f"(b.y));
    return r;
}
__device__ __forceinline__ float2 f2ma(float2 a, float2 b, float2 c) {
    float2 r;
    asm("{.reg .b64 ra,rb,rc,rd;\n\t"
        "mov.b64 ra,{%2,%3};\n\t"
        "mov.b64 rb,{%4,%5};\n\t"
        "mov.b64 rc,{%6,%7};\n\t"
        "fma.rn.f32x2 rd,ra,rb,rc;\n\t"
        "mov.b64 {%0,%1},rd;}\n\t"
        : "=f"(r.x), "=f"(r.y)
        : "f"(a.x), "f"(a.y), "f"(b.x), "f"(b.y), "f"(c.x), "f"(c.y));
    return r;
}

__global__ void zero_out_kernel(float* out, int n) {
    int i = blockIdx.x * blockDim.x + threadIdx.x;
    if (i < n) out[i] = 0.0f;
}

__global__ __launch_bounds__(32 * BYT, 2)
void lcc_kernel(const float* __restrict__ gF,
                const float* __restrict__ gM,
                float* __restrict__ out)
{
    __shared__ float2 sA [COVY][33];
    __shared__ float2 sB [COVY][33];
    __shared__ float2 sQ0[COVY][33];
    __shared__ float2 sQ1[COVY][33];
    __shared__ float2 sQ2[COVY][33];
    __shared__ float  wsum[BYT];

    const int tx = threadIdx.x;
    const int ty = threadIdx.y;
    const int b  = blockIdx.z / ZCHUNKS;
    const int Z0 = (blockIdx.z % ZCHUNKS) * ZC;

    const int x_nom0 = (int)blockIdx.x * TOUTX - 2 + 2 * tx;   // even
    const int xbase  = min(max(x_nom0, 0), NV - 2);
    const bool fixlo  = (x_nom0 < 0);
    const bool fixhi  = (x_nom0 > NV - 2);
    const bool fixXlo = (x_nom0 == 0);
    const bool fixXhi = (x_nom0 + 1 == NV - 1);

    const int y_nom = (int)blockIdx.y * TOUTY - 2 + ty;
    const bool fixYup = (y_nom == 0);
    const bool fixYdn = (y_nom == NV - 1);
    const int yoff = min(max(y_nom, 0), NV - 1) * NV + xbase;

    const float* F = gF + (long long)b * NV3;
    const float* M = gM + (long long)b * NV3;

    float2 rF[3], rM[3];               // raw plane ring
    float2 pA[3], pB[3], pC[3];        // P plane ring (FM, FF, MM)
    float2 acc = make_float2(0.f, 0.f);

    const float2 NEGI = make_float2(-INV27, -INV27);
    const float2 EPS2 = make_float2(EPSV, EPSV);

    const float mk = (tx >= 1 && tx <= 24 && ty >= 2 && ty < 2 + TOUTY) ? 1.0f : 0.0f;
    const float2 mask = make_float2(mk, mk);

    const int rup = ty ? ty - 1 : 0;
    const int rdn = (ty + 1 < COVY) ? ty + 1 : COVY - 1;

    auto loadp = [&](int z, int s) {
        z = min(max(z, 0), NV - 1);
        const float* fp = F + z * NV2;
        const float* mp = M + z * NV2;
        float2 vF = __ldg(reinterpret_cast<const float2*>(fp + yoff));
        float2 vM = __ldg(reinterpret_cast<const float2*>(mp + yoff));
        rF[s].x = fixhi ? vF.y : vF.x;  rF[s].y = fixlo ? vF.x : vF.y;
        rM[s].x = fixhi ? vM.y : vM.x;  rM[s].y = fixlo ? vM.x : vM.y;
    };

    // P for the plane in raw slot i1 (i0,i1,i2 = planes c-1,c,c+1) -> P slot qw.
    auto stepP = [&](int i0, int i1, int i2, int qw) {
        float2 zf = a2(a2(rF[i0], rF[i1]), rF[i2]);
        float2 zm = a2(a2(rM[i0], rM[i1]), rM[i2]);
        sA[ty][tx] = zf;
        sB[ty][tx] = zm;
        __syncthreads();
        float2 upF = sA[rup][tx], dnF = sA[rdn][tx];
        float2 upM = sB[rup][tx], dnM = sB[rdn][tx];
        float2 yf = a2(a2(upF, zf), dnF);
        float2 ym = a2(a2(upM, zm), dnM);
        float lF = __shfl_up_sync(FULL, yf.y, 1);
        float rG = __shfl_down_sync(FULL, yf.x, 1);
        float pF = yf.x + yf.y;
        float2 sF = make_float2(lF + pF, pF + rG);
        float lM = __shfl_up_sync(FULL, ym.y, 1);
        float rH = __shfl_down_sync(FULL, ym.x, 1);
        float pM = ym.x + ym.y;
        float2 sM = make_float2(lM + pM, pM + rH);
        float2 dF = f2ma(sF, NEGI, rF[i1]);
        float2 dM = f2ma(sM, NEGI, rM[i1]);
        pA[qw] = m2(dF, dM);
        pB[qw] = m2(dF, dF);
        pC[qw] = m2(dM, dM);
    };

    // box over P slots (i0,i1,i2) = P(j-1),P(j),P(j+1); score plane j.
    auto box2 = [&](int i0, int i1, int i2) {
        float2 zA = a2(a2(pA[i0], pA[i1]), pA[i2]);
        float2 zB = a2(a2(pB[i0], pB[i1]), pB[i2]);
        float2 zD = a2(a2(pC[i0], pC[i1]), pC[i2]);
        sQ0[ty][tx] = zA;
        sQ1[ty][tx] = zB;
        sQ2[ty][tx] = zD;
        __syncthreads();
        float2 uA = sQ0[rup][tx], dA = sQ0[rdn][tx];
        float2 uB = sQ1[rup][tx], dB = sQ1[rdn][tx];
        float2 uD = sQ2[rup][tx], dD = sQ2[rdn][tx];
        uA = fixYup ? zA : uA;  dA = fixYdn ? zA : dA;
        uB = fixYup ? zB : uB;  dB = fixYdn ? zB : dB;
        uD = fixYup ? zD : uD;  dD = fixYdn ? zD : dD;
        float2 ybA = a2(a2(uA, zA), dA);
        float2 ybB = a2(a2(uB, zB), dB);
        float2 ybD = a2(a2(uD, zD), dD);
        float lA = __shfl_up_sync(FULL, ybA.y, 1);
        float rA = __shfl_down_sync(FULL, ybA.x, 1);
        float pA_ = ybA.x + ybA.y;
        float2 crA = make_float2((fixXlo ? ybA.x : lA) + pA_,
                                 pA_ + (fixXhi ? ybA.y : rA));
        float lB = __shfl_up_sync(FULL, ybB.y, 1);
        float rB = __shfl_down_sync(FULL, ybB.x, 1);
        float pB_ = ybB.x + ybB.y;
        float2 crB = make_float2((fixXlo ? ybB.x : lB) + pB_,
                                 pB_ + (fixXhi ? ybB.y : rB));
        float lD = __shfl_up_sync(FULL, ybD.y, 1);
        float rD = __shfl_down_sync(FULL, ybD.x, 1);
        float pD_ = ybD.x + ybD.y;
        float2 crD = make_float2((fixXlo ? ybD.x : lD) + pD_,
                                 pD_ + (fixXhi ? ybD.y : rD));
        float2 num = m2(crA, crA);
        float2 den = f2ma(crB, crD, EPS2);
        float2 zv  = make_float2(__fdividef(num.x, den.x),
                                 __fdividef(num.y, den.y));
        acc = f2ma(zv, mask, acc);
    };

    // ---- Prologue: raw slots end (0:Z0+1, 1:Z0+2, 2:Z0); P slots P(Z0-1..Z0+1) ----
    if (Z0 == 0) {
        loadp(0, 2);
        loadp(1, 0);
        rF[1] = rF[2]; rM[1] = rM[2];
        stepP(1, 2, 0, 1);   // P(0): zsum = 2*r(0)+r(1), center r(0)
        pA[0] = pA[1]; pB[0] = pB[1]; pC[0] = pC[1];   // P(-1) := P(0)
        __syncthreads();     // fence sA reads vs next stepP writes
        loadp(2, 1);
        stepP(2, 0, 1, 2);   // P(1)
    } else {
        loadp(Z0 - 2, 0);
        loadp(Z0 - 1, 1);
        loadp(Z0,     2);
        stepP(0, 1, 2, 0);   // P(Z0-1)
        __syncthreads();
        loadp(Z0 + 1, 0);
        stepP(1, 2, 0, 1);   // P(Z0)
        __syncthreads();
        loadp(Z0 + 2, 1);
        stepP(2, 0, 1, 2);   // P(Z0+1)
    }

    const int zlast = Z0 + ZC - 1;

    // ---- Main body. Entry: raw (s0,s1,s2) = planes (j+1, j+2, j), P = P(j-1..j+1).
    auto body = [&](int j, int s0, int s1, int s2) {
        loadp(j + 3, s2);        // overwrite oldest raw (plane j); clamped
        box2(s0, s1, s2);        // score plane j (P slots)
        if (j < zlast) {
            if (j + 2 < NV) {
                stepP(s0, s1, s2, s0);   // P(j+2) from raw (j+1,j+2,j+3)
            } else {
                __syncthreads();         // fence sQ reads vs next box2 writes
                pA[s0] = pA[s2]; pB[s0] = pB[s2]; pC[s0] = pC[s2];  // P(j+2):=P(NV-1)
            }
        }
    };

    for (int kb = 0; kb < ZC; kb += 3) {
        body(Z0 + kb,     0, 1, 2);
        body(Z0 + kb + 1, 1, 2, 0);
        body(Z0 + kb + 2, 2, 0, 1);
    }

    // ---- Reduction ----
    float t = acc.x + acc.y;
#pragma unroll
    for (int o = 16; o > 0; o >>= 1)
        t += __shfl_xor_sync(FULL, t, o);
    if (tx == 0) wsum[ty] = t;
    __syncthreads();
    if (tx == 0 && ty == 0) {
        float s = 0.0f;
#pragma unroll
        for (int i = 0; i < BYT; i++) s += wsum[i];
        atomicAdd(&out[b], s * (-1.0f / (float)NV3));
    }
}

extern "C" void kernel_launch(void* const* d_in, const int* in_sizes, int n_in,
                              void* d_out, int out_size) {
    const float* F = (const float*)d_in[0];
    const float* M = (const float*)d_in[1];
    float* out = (float*)d_out;

    const int B = (int)(in_sizes[0] / (long long)NV3);

    zero_out_kernel<<<1, 32>>>(out, out_size);

    dim3 block(32, BYT, 1);
    dim3 grid(NV / TOUTX, NV / TOUTY, B * ZCHUNKS);
    lcc_kernel<<<grid, block>>>(F, M, out);
}